// round 3
// baseline (speedup 1.0000x reference)
#include <cuda_runtime.h>
#include <cstdint>
#include <cstddef>

// Problem constants
#define T_STEPS 50000
#define DIN     768     // lstm input dim (6*F)
#define HGATE   512     // 4*F gate rows of lstm2
#define FDIM    128     // hidden size of lstm2 / feature dim

// Scratch (device globals; no allocations allowed)
__device__ float g_pre2[(size_t)T_STEPS * HGATE];  // 102.4 MB
__device__ float g_hs2 [(size_t)T_STEPS * FDIM];   //  25.6 MB

typedef unsigned long long ull;

// ---------------------------------------------------------------------------
// helpers
// ---------------------------------------------------------------------------
__device__ __forceinline__ void ffma2(ull& d, ull a, ull b) {
    // packed fp32x2 FMA (sm_100+)
    asm("fma.rn.f32x2 %0, %1, %2, %3;" : "=l"(d) : "l"(a), "l"(b), "l"(d));
}
__device__ __forceinline__ ull fadd2(ull a, ull b) {
    ull d; asm("add.rn.f32x2 %0, %1, %2;" : "=l"(d) : "l"(a), "l"(b)); return d;
}
__device__ __forceinline__ float sigf(float x) {
    return __fdividef(1.0f, 1.0f + __expf(-x));
}
__device__ __forceinline__ float tanh_fast(float x) {
    return fmaf(2.0f, sigf(2.0f * x), -1.0f);
}
__device__ __forceinline__ uint32_t smem_u32(const void* p) {
    uint32_t a;
    asm("{ .reg .u64 t; cvta.to.shared.u64 t, %1; cvt.u32.u64 %0, t; }"
        : "=r"(a) : "l"(p));
    return a;
}

// ---------------------------------------------------------------------------
// Generic tiled GEMM: C[M,N] = A[M,K] @ W[N,K]^T + b1[N] (+ b2[N]) (+sigmoid)
// BM=BN=64, BK=16, 256 threads, 4x4 microtile per thread.
// ---------------------------------------------------------------------------
template <bool SIG, bool HASB2>
__global__ __launch_bounds__(256)
void gemm_kernel(const float* __restrict__ A, const float* __restrict__ W,
                 const float* __restrict__ b1, const float* __restrict__ b2,
                 float* __restrict__ C, int M, int N, int K)
{
    __shared__ float As[16][68];
    __shared__ float Bs[16][68];

    const int tid = threadIdx.x;
    const int tx  = tid & 15;
    const int ty  = tid >> 4;
    const int m0  = blockIdx.y * 64;
    const int n0  = blockIdx.x * 64;

    const int lr = tid >> 2;          // 0..63 : row within tile
    const int lk = (tid & 3) * 4;     // 0,4,8,12 : k offset (float4)

    const int arow = m0 + lr;
    const int brow = n0 + lr;
    const bool avalid = (arow < M);
    const float* aptr = A + (size_t)arow * K + lk;
    const float* bptr = W + (size_t)brow * K + lk;

    float acc[4][4] = {};

    for (int k0 = 0; k0 < K; k0 += 16) {
        float4 av = avalid ? *(const float4*)(aptr + k0) : make_float4(0.f, 0.f, 0.f, 0.f);
        float4 bv = *(const float4*)(bptr + k0);
        As[lk + 0][lr] = av.x; As[lk + 1][lr] = av.y;
        As[lk + 2][lr] = av.z; As[lk + 3][lr] = av.w;
        Bs[lk + 0][lr] = bv.x; Bs[lk + 1][lr] = bv.y;
        Bs[lk + 2][lr] = bv.z; Bs[lk + 3][lr] = bv.w;
        __syncthreads();
        #pragma unroll
        for (int kk = 0; kk < 16; ++kk) {
            float4 a = *(const float4*)&As[kk][ty * 4];
            float4 b = *(const float4*)&Bs[kk][tx * 4];
            acc[0][0] = fmaf(a.x, b.x, acc[0][0]);
            acc[0][1] = fmaf(a.x, b.y, acc[0][1]);
            acc[0][2] = fmaf(a.x, b.z, acc[0][2]);
            acc[0][3] = fmaf(a.x, b.w, acc[0][3]);
            acc[1][0] = fmaf(a.y, b.x, acc[1][0]);
            acc[1][1] = fmaf(a.y, b.y, acc[1][1]);
            acc[1][2] = fmaf(a.y, b.z, acc[1][2]);
            acc[1][3] = fmaf(a.y, b.w, acc[1][3]);
            acc[2][0] = fmaf(a.z, b.x, acc[2][0]);
            acc[2][1] = fmaf(a.z, b.y, acc[2][1]);
            acc[2][2] = fmaf(a.z, b.z, acc[2][2]);
            acc[2][3] = fmaf(a.z, b.w, acc[2][3]);
            acc[3][0] = fmaf(a.w, b.x, acc[3][0]);
            acc[3][1] = fmaf(a.w, b.y, acc[3][1]);
            acc[3][2] = fmaf(a.w, b.z, acc[3][2]);
            acc[3][3] = fmaf(a.w, b.w, acc[3][3]);
        }
        __syncthreads();
    }

    float bias[4];
    #pragma unroll
    for (int j = 0; j < 4; ++j) {
        int col = n0 + tx * 4 + j;
        bias[j] = b1[col];
        if (HASB2) bias[j] += b2[col];
    }
    #pragma unroll
    for (int i = 0; i < 4; ++i) {
        int row = m0 + ty * 4 + i;
        if (row < M) {
            float4 v;
            v.x = acc[i][0] + bias[0];
            v.y = acc[i][1] + bias[1];
            v.z = acc[i][2] + bias[2];
            v.w = acc[i][3] + bias[3];
            if (SIG) { v.x = sigf(v.x); v.y = sigf(v.y); v.z = sigf(v.z); v.w = sigf(v.w); }
            *(float4*)(C + (size_t)row * N + n0 + tx * 4) = v;
        }
    }
}

// ---------------------------------------------------------------------------
// LSTM2 scan: 2-CTA cluster, lockstep recurrence.
// Thread mapping: q = tid>>2 (unit in CTA, 0..63), g = tid&3 (gate).
// Gate row = g*128 + rank*64 + q. The 4 gate values of one unit sit in
// adjacent lanes of one warp -> shfl_down gather (no smem staging).
// Each thread's 128-float Whh row lives in registers, split local-64/peer-64;
// the peer-wait (mbarrier) sits between the halves to hide DSMEM latency.
// ---------------------------------------------------------------------------
__global__ void __cluster_dims__(2, 1, 1) __launch_bounds__(256, 1)
scan_kernel(const float* __restrict__ pre2, const float* __restrict__ Whh,
            const float* __restrict__ h0,   const float* __restrict__ c0,
            float* __restrict__ hs2)
{
    __shared__ __align__(16) float h_buf[2][FDIM];
    __shared__ __align__(8) unsigned long long mbar[1];

    const int tid = threadIdx.x;
    uint32_t rank; asm("mov.u32 %0, %%cluster_ctarank;" : "=r"(rank));
    const uint32_t peer = rank ^ 1u;

    const int q   = tid >> 2;                       // unit within CTA (0..63)
    const int g   = tid & 3;                        // 0:i 1:f 2:g 3:o
    const int row = g * 128 + (int)rank * 64 + q;   // gate row in [0,512)
    const int m   = (int)rank * 64 + q;             // owned hidden unit
    const bool owner = (g == 0);

    const int own_base  = (int)rank * 64;           // this CTA's h segment
    const int peer_base = (int)peer * 64;

    // Whh row -> registers: w[0..31] = own-half cols, w[32..63] = peer-half
    ull w[64];
    {
        const ull* wown = (const ull*)(Whh + (size_t)row * FDIM + own_base);
        const ull* wpr  = (const ull*)(Whh + (size_t)row * FDIM + peer_base);
        #pragma unroll
        for (int i = 0; i < 32; ++i) w[i]      = wown[i];
        #pragma unroll
        for (int i = 0; i < 32; ++i) w[32 + i] = wpr[i];
    }

    const uint32_t mbar_addr = smem_u32(mbar);
    uint32_t mbar_remote;
    asm("mapa.shared::cluster.u32 %0, %1, %2;" : "=r"(mbar_remote) : "r"(mbar_addr), "r"(peer));

    if (tid == 0) {
        asm volatile("mbarrier.init.shared.b64 [%0], %1;" :: "r"(mbar_addr), "r"(64) : "memory");
    }
    if (tid < FDIM) h_buf[1][tid] = h0[tid];   // step 0 reads buffer 1
    float c = 0.0f;
    if (owner) c = c0[m];

    // Remote smem addresses of this owner's h slot, both parities
    uint32_t h_rem0 = 0, h_rem1 = 0;
    {
        uint32_t l0 = smem_u32(&h_buf[0][m]);
        uint32_t l1 = smem_u32(&h_buf[1][m]);
        asm("mapa.shared::cluster.u32 %0, %1, %2;" : "=r"(h_rem0) : "r"(l0), "r"(peer));
        asm("mapa.shared::cluster.u32 %0, %1, %2;" : "=r"(h_rem1) : "r"(l1), "r"(peer));
    }

    __syncthreads();
    // mbarriers + initial h visible cluster-wide before any remote traffic
    asm volatile("barrier.cluster.arrive.aligned;" ::: "memory");
    asm volatile("barrier.cluster.wait.aligned;"   ::: "memory");

    // distance-2 prefetch of pre-activations (covers DRAM latency)
    float pre_next  = pre2[row];                         // t = 0
    float pre_next2 = pre2[(size_t)HGATE + row];         // t = 1
    const float two = 2.0f;

    #pragma unroll 1
    for (int t = 0; t < T_STEPS; ++t) {
        const int p  = t & 1;       // buffer written this step (h[t])
        const int rp = p ^ 1;       // buffer read this step    (h[t-1])

        float pre_cur = pre_next;
        pre_next = pre_next2;
        {   // prefetch step t+2
            int tn = (t + 2 < T_STEPS) ? (t + 2) : (T_STEPS - 1);
            pre_next2 = __ldg(&pre2[(size_t)tn * HGATE + row]);
        }

        // ---- local half of Whh_row . h  (ready right after last BAR) ----
        ull acc0 = 0, acc1 = 0, acc2 = 0, acc3 = 0;
        const ull* hl = (const ull*)&h_buf[rp][own_base];
        #pragma unroll
        for (int i = 0; i < 8; ++i) {
            ffma2(acc0, w[4 * i + 0], hl[4 * i + 0]);
            ffma2(acc1, w[4 * i + 1], hl[4 * i + 1]);
            ffma2(acc2, w[4 * i + 2], hl[4 * i + 2]);
            ffma2(acc3, w[4 * i + 3], hl[4 * i + 3]);
        }

        // ---- wait for peer's h[t-1] half (skipped at t=0: h0 prestored) ----
        if (t > 0) {
            uint32_t par = (uint32_t)((t - 1) & 1);
            asm volatile(
                "{\n\t.reg .pred P;\n"
                "W0_%=:\n\t"
                "mbarrier.try_wait.parity.acquire.cluster.shared::cta.b64 P, [%0], %1, 0x989680;\n\t"
                "@P bra W1_%=;\n\t"
                "bra W0_%=;\n"
                "W1_%=:\n\t}"
                :: "r"(mbar_addr), "r"(par) : "memory");
        }

        // ---- peer half ----
        const ull* hp = (const ull*)&h_buf[rp][peer_base];
        #pragma unroll
        for (int i = 0; i < 8; ++i) {
            ffma2(acc0, w[32 + 4 * i + 0], hp[4 * i + 0]);
            ffma2(acc1, w[32 + 4 * i + 1], hp[4 * i + 1]);
            ffma2(acc2, w[32 + 4 * i + 2], hp[4 * i + 2]);
            ffma2(acc3, w[32 + 4 * i + 3], hp[4 * i + 3]);
        }
        ull s = fadd2(fadd2(acc0, acc1), fadd2(acc2, acc3));
        float lo = __uint_as_float((uint32_t)s);
        float hi = __uint_as_float((uint32_t)(s >> 32));
        float gate = pre_cur + lo + hi;

        // branch-free activation: sigmoid for i,f,o; tanh for g (= 2*sig(2x)-1)
        float xs = (g == 2) ? two * gate : gate;
        float sv = sigf(xs);
        float a  = (g == 2) ? fmaf(two, sv, -1.0f) : sv;

        // gather gate quad at owner lanes (lane%4==0); shfl syncs the warp,
        // so all reads of h_buf[rp] complete before owners signal the peer.
        float af = __shfl_down_sync(0xffffffffu, a, 1);
        float ag = __shfl_down_sync(0xffffffffu, a, 2);
        float ao = __shfl_down_sync(0xffffffffu, a, 3);

        if (owner) {
            c = fmaf(af, c, a * ag);            // a == i for owner lanes
            float h = ao * tanh_fast(c);
            h_buf[p][m] = h;                    // local copy
            uint32_t hr = p ? h_rem1 : h_rem0;  // peer copy via DSMEM
            asm volatile("st.shared::cluster.f32 [%0], %1;" :: "r"(hr), "f"(h) : "memory");
            asm volatile("mbarrier.arrive.release.cluster.shared::cluster.b64 _, [%0];"
                         :: "r"(mbar_remote) : "memory");
            hs2[(size_t)t * FDIM + m] = h;      // for fc GEMM
        }
        __syncthreads();                         // local h[t] visible CTA-wide
    }

    // Do not exit while peer DSMEM traffic may be in flight
    asm volatile("barrier.cluster.arrive.aligned;" ::: "memory");
    asm volatile("barrier.cluster.wait.aligned;"   ::: "memory");
}

// ---------------------------------------------------------------------------
// launch
// ---------------------------------------------------------------------------
extern "C" void kernel_launch(void* const* d_in, const int* in_sizes, int n_in,
                              void* d_out, int out_size)
{
    (void)in_sizes; (void)n_in; (void)out_size;
    // metadata order: x,h1,c1,h2,c2, Wih1,Whh1,bih1,bhh1, Wih2,Whh2,bih2,bhh2, Wfc,bfc
    const float* x    = (const float*)d_in[0];
    const float* h2   = (const float*)d_in[3];
    const float* c2   = (const float*)d_in[4];
    const float* Wih2 = (const float*)d_in[9];
    const float* Whh2 = (const float*)d_in[10];
    const float* bih2 = (const float*)d_in[11];
    const float* bhh2 = (const float*)d_in[12];
    const float* Wfc  = (const float*)d_in[13];
    const float* bfc  = (const float*)d_in[14];
    float* out = (float*)d_out;

    float* pre2; cudaGetSymbolAddress((void**)&pre2, g_pre2);
    float* hs2;  cudaGetSymbolAddress((void**)&hs2,  g_hs2);

    const int mblocks = (T_STEPS + 63) / 64;   // 782

    // 1) pre2 = x @ Wih2^T + (bih2 + bhh2)   (lstm1 is dead code — skipped)
    gemm_kernel<false, true><<<dim3(HGATE / 64, mblocks), 256>>>(
        x, Wih2, bih2, bhh2, pre2, T_STEPS, HGATE, DIN);

    // 2) sequential LSTM scan over 50000 steps (2-CTA cluster, reg-resident Whh)
    scan_kernel<<<2, 256>>>(pre2, Whh2, h2, c2, hs2);

    // 3) out = sigmoid(hs2 @ Wfc^T + bfc)
    gemm_kernel<true, false><<<dim3(FDIM / 64, mblocks), 256>>>(
        hs2, Wfc, bfc, nullptr, out, T_STEPS, FDIM, FDIM);
}

// round 4
// speedup vs baseline: 1.6379x; 1.6379x over previous
#include <cuda_runtime.h>
#include <cstdint>
#include <cstddef>

// Problem constants
#define T_STEPS 50000
#define DIN     768     // lstm input dim (6*F)
#define HGATE   512     // 4*F gate rows of lstm2
#define FDIM    128     // hidden size of lstm2 / feature dim

// Scratch (device globals; no allocations allowed)
__device__ float g_pre2[(size_t)T_STEPS * HGATE];  // 102.4 MB
__device__ float g_hs2 [(size_t)T_STEPS * FDIM];   //  25.6 MB

typedef unsigned long long ull;

// ---------------------------------------------------------------------------
// helpers
// ---------------------------------------------------------------------------
__device__ __forceinline__ void ffma2(ull& d, ull a, ull b) {
    asm("fma.rn.f32x2 %0, %1, %2, %3;" : "=l"(d) : "l"(a), "l"(b), "l"(d));
}
__device__ __forceinline__ ull fadd2(ull a, ull b) {
    ull d; asm("add.rn.f32x2 %0, %1, %2;" : "=l"(d) : "l"(a), "l"(b)); return d;
}
__device__ __forceinline__ float sigf(float x) {
    return __fdividef(1.0f, 1.0f + __expf(-x));
}
__device__ __forceinline__ float tanh_fast(float x) {
    return fmaf(2.0f, sigf(2.0f * x), -1.0f);
}
__device__ __forceinline__ uint32_t smem_u32(const void* p) {
    uint32_t a;
    asm("{ .reg .u64 t; cvta.to.shared.u64 t, %1; cvt.u32.u64 %0, t; }"
        : "=r"(a) : "l"(p));
    return a;
}
__device__ __forceinline__ uint32_t mapa_u32(uint32_t addr, uint32_t rank) {
    uint32_t r;
    asm("mapa.shared::cluster.u32 %0, %1, %2;" : "=r"(r) : "r"(addr), "r"(rank));
    return r;
}
__device__ __forceinline__ void mbar_expect(uint32_t mbar, uint32_t bytes) {
    asm volatile("mbarrier.arrive.expect_tx.shared.b64 _, [%0], %1;"
                 :: "r"(mbar), "r"(bytes) : "memory");
}
__device__ __forceinline__ void mbar_wait(uint32_t mbar, uint32_t parity) {
    asm volatile(
        "{\n\t.reg .pred P;\n"
        "LW_%=:\n\t"
        "mbarrier.try_wait.parity.shared::cta.b64 P, [%0], %1;\n\t"
        "@P bra LD_%=;\n\t"
        "bra LW_%=;\n"
        "LD_%=:\n\t}"
        :: "r"(mbar), "r"(parity) : "memory");
}
// async store with transaction-count completion on the destination barrier
__device__ __forceinline__ void st_async_f32(uint32_t dst, float v, uint32_t mbar) {
    asm volatile("st.async.shared::cluster.mbarrier::complete_tx::bytes.f32 [%0], %1, [%2];"
                 :: "r"(dst), "f"(v), "r"(mbar) : "memory");
}

// ---------------------------------------------------------------------------
// Generic tiled GEMM: C[M,N] = A[M,K] @ W[N,K]^T + b1[N] (+ b2[N]) (+sigmoid)
// ---------------------------------------------------------------------------
template <bool SIG, bool HASB2>
__global__ __launch_bounds__(256)
void gemm_kernel(const float* __restrict__ A, const float* __restrict__ W,
                 const float* __restrict__ b1, const float* __restrict__ b2,
                 float* __restrict__ C, int M, int N, int K)
{
    __shared__ float As[16][68];
    __shared__ float Bs[16][68];

    const int tid = threadIdx.x;
    const int tx  = tid & 15;
    const int ty  = tid >> 4;
    const int m0  = blockIdx.y * 64;
    const int n0  = blockIdx.x * 64;

    const int lr = tid >> 2;
    const int lk = (tid & 3) * 4;

    const int arow = m0 + lr;
    const int brow = n0 + lr;
    const bool avalid = (arow < M);
    const float* aptr = A + (size_t)arow * K + lk;
    const float* bptr = W + (size_t)brow * K + lk;

    float acc[4][4] = {};

    for (int k0 = 0; k0 < K; k0 += 16) {
        float4 av = avalid ? *(const float4*)(aptr + k0) : make_float4(0.f, 0.f, 0.f, 0.f);
        float4 bv = *(const float4*)(bptr + k0);
        As[lk + 0][lr] = av.x; As[lk + 1][lr] = av.y;
        As[lk + 2][lr] = av.z; As[lk + 3][lr] = av.w;
        Bs[lk + 0][lr] = bv.x; Bs[lk + 1][lr] = bv.y;
        Bs[lk + 2][lr] = bv.z; Bs[lk + 3][lr] = bv.w;
        __syncthreads();
        #pragma unroll
        for (int kk = 0; kk < 16; ++kk) {
            float4 a = *(const float4*)&As[kk][ty * 4];
            float4 b = *(const float4*)&Bs[kk][tx * 4];
            acc[0][0] = fmaf(a.x, b.x, acc[0][0]);
            acc[0][1] = fmaf(a.x, b.y, acc[0][1]);
            acc[0][2] = fmaf(a.x, b.z, acc[0][2]);
            acc[0][3] = fmaf(a.x, b.w, acc[0][3]);
            acc[1][0] = fmaf(a.y, b.x, acc[1][0]);
            acc[1][1] = fmaf(a.y, b.y, acc[1][1]);
            acc[1][2] = fmaf(a.y, b.z, acc[1][2]);
            acc[1][3] = fmaf(a.y, b.w, acc[1][3]);
            acc[2][0] = fmaf(a.z, b.x, acc[2][0]);
            acc[2][1] = fmaf(a.z, b.y, acc[2][1]);
            acc[2][2] = fmaf(a.z, b.z, acc[2][2]);
            acc[2][3] = fmaf(a.z, b.w, acc[2][3]);
            acc[3][0] = fmaf(a.w, b.x, acc[3][0]);
            acc[3][1] = fmaf(a.w, b.y, acc[3][1]);
            acc[3][2] = fmaf(a.w, b.z, acc[3][2]);
            acc[3][3] = fmaf(a.w, b.w, acc[3][3]);
        }
        __syncthreads();
    }

    float bias[4];
    #pragma unroll
    for (int j = 0; j < 4; ++j) {
        int col = n0 + tx * 4 + j;
        bias[j] = b1[col];
        if (HASB2) bias[j] += b2[col];
    }
    #pragma unroll
    for (int i = 0; i < 4; ++i) {
        int row = m0 + ty * 4 + i;
        if (row < M) {
            float4 v;
            v.x = acc[i][0] + bias[0];
            v.y = acc[i][1] + bias[1];
            v.z = acc[i][2] + bias[2];
            v.w = acc[i][3] + bias[3];
            if (SIG) { v.x = sigf(v.x); v.y = sigf(v.y); v.z = sigf(v.z); v.w = sigf(v.w); }
            *(float4*)(C + (size_t)row * N + n0 + tx * 4) = v;
        }
    }
}

// ---------------------------------------------------------------------------
// LSTM2 scan: 2-CTA cluster, lockstep recurrence, st.async transaction-tracked
// h exchange. No __syncthreads and no per-thread remote arrives in the loop.
//
// Mapping: q = tid>>2 (unit in CTA, 0..63), g = tid&3 (gate i/f/g/o).
// Gate row = g*128 + rank*64 + q; owner lane (g==0) finalizes unit m.
// Per step each of the 64 owners delivers h[m] twice via st.async.f32:
//   - into own   h_buf[slot][m], credited to own  bar_loc[slot]  (256 B)
//   - into peer  h_buf[slot][m], credited to peer bar_rem[slot]  (256 B)
// tid0 posts arrive.expect_tx(256) on bar_loc[slot] & bar_rem[slot] each step.
// Consumers wait bar_loc first (fast), run the local-half FFMAs, then wait
// bar_rem — the ~215cyc DSMEM flight is hidden behind the local half.
// ---------------------------------------------------------------------------
__global__ void __cluster_dims__(2, 1, 1) __launch_bounds__(256, 1)
scan_kernel(const float* __restrict__ pre2, const float* __restrict__ Whh,
            const float* __restrict__ h0,   const float* __restrict__ c0,
            float* __restrict__ hs2)
{
    __shared__ __align__(16) float h_buf[2][FDIM];
    __shared__ __align__(8) unsigned long long bar_loc[2];
    __shared__ __align__(8) unsigned long long bar_rem[2];

    const int tid = threadIdx.x;
    uint32_t rank; asm("mov.u32 %0, %%cluster_ctarank;" : "=r"(rank));
    const uint32_t peer = rank ^ 1u;

    const int q   = tid >> 2;                       // unit within CTA (0..63)
    const int g   = tid & 3;                        // 0:i 1:f 2:g 3:o
    const int row = g * 128 + (int)rank * 64 + q;   // gate row in [0,512)
    const int m   = (int)rank * 64 + q;             // owned hidden unit
    const bool owner = (g == 0);

    const int own_base  = (int)rank * 64;           // this CTA's h segment
    const int peer_base = (int)peer * 64;

    // Whh row -> registers: w[0..31] own-half cols, w[32..63] peer-half cols
    ull w[64];
    {
        const ull* wa = (const ull*)(Whh + (size_t)row * FDIM + own_base);
        const ull* wb = (const ull*)(Whh + (size_t)row * FDIM + peer_base);
        #pragma unroll
        for (int i = 0; i < 32; ++i) w[i]      = wa[i];
        #pragma unroll
        for (int i = 0; i < 32; ++i) w[32 + i] = wb[i];
    }

    const uint32_t bl0 = smem_u32(&bar_loc[0]);
    const uint32_t bl1 = smem_u32(&bar_loc[1]);
    const uint32_t br0 = smem_u32(&bar_rem[0]);
    const uint32_t br1 = smem_u32(&bar_rem[1]);

    if (tid == 0) {
        asm volatile("mbarrier.init.shared.b64 [%0], %1;" :: "r"(bl0), "r"(1) : "memory");
        asm volatile("mbarrier.init.shared.b64 [%0], %1;" :: "r"(bl1), "r"(1) : "memory");
        asm volatile("mbarrier.init.shared.b64 [%0], %1;" :: "r"(br0), "r"(1) : "memory");
        asm volatile("mbarrier.init.shared.b64 [%0], %1;" :: "r"(br1), "r"(1) : "memory");
    }
    if (tid < FDIM) h_buf[1][tid] = h0[tid];        // step 0 reads slot 1
    float c = 0.0f;
    if (owner) c = c0[m];

    // Owner destinations (cluster address space), both parities.
    // Local deliveries credit own bar_loc; remote deliveries credit peer bar_rem.
    uint32_t la0 = 0, la1 = 0, ra0 = 0, ra1 = 0;
    uint32_t lb0c = 0, lb1c = 0, rb0c = 0, rb1c = 0;
    if (owner) {
        uint32_t a0 = smem_u32(&h_buf[0][m]);
        uint32_t a1 = smem_u32(&h_buf[1][m]);
        la0 = mapa_u32(a0, rank);  la1 = mapa_u32(a1, rank);
        ra0 = mapa_u32(a0, peer);  ra1 = mapa_u32(a1, peer);
        lb0c = mapa_u32(bl0, rank); lb1c = mapa_u32(bl1, rank);
        rb0c = mapa_u32(br0, peer); rb1c = mapa_u32(br1, peer);
    }

    __syncthreads();
    asm volatile("fence.proxy.async.shared::cta;" ::: "memory");
    // barriers + initial h visible cluster-wide before any remote traffic
    asm volatile("barrier.cluster.arrive.aligned;" ::: "memory");
    asm volatile("barrier.cluster.wait.aligned;"   ::: "memory");

    // distance-2 prefetch of pre-activations
    const float* prow = pre2 + row;
    float pre_next  = prow[0];
    float pre_next2 = prow[HGATE];
    const float two = 2.0f;

    #pragma unroll 1
    for (int t = 0; t < T_STEPS; ++t) {
        const int slot  = t & 1;        // slot written this step (h[t])
        const int rslot = slot ^ 1;     // slot read this step (h[t-1])

        // Re-arm this step's delivery barriers (prior phase observed at t-1).
        if (tid == 0) {
            mbar_expect(slot ? bl1 : bl0, 256);
            mbar_expect(slot ? br1 : br0, 256);
        }

        float pre_cur = pre_next;
        pre_next = pre_next2;
        {
            int tn = (t + 2 < T_STEPS) ? (t + 2) : (T_STEPS - 1);
            pre_next2 = __ldg(&prow[(size_t)tn * HGATE]);
        }

        const uint32_t parity = (uint32_t)(((t - 1) >> 1) & 1);

        // ---- local half (own CTA's 64 h values; fast local delivery) ----
        if (t > 0) mbar_wait(rslot ? bl1 : bl0, parity);
        ull acc0 = 0, acc1 = 0, acc2 = 0, acc3 = 0;
        {
            const ulonglong2* hl = (const ulonglong2*)&h_buf[rslot][own_base];
            #pragma unroll
            for (int i = 0; i < 8; ++i) {
                ulonglong2 va = hl[2 * i];
                ulonglong2 vb = hl[2 * i + 1];
                ffma2(acc0, w[4 * i + 0], va.x);
                ffma2(acc1, w[4 * i + 1], va.y);
                ffma2(acc2, w[4 * i + 2], vb.x);
                ffma2(acc3, w[4 * i + 3], vb.y);
            }
        }

        // ---- peer half (DSMEM flight hidden behind local half) ----
        if (t > 0) mbar_wait(rslot ? br1 : br0, parity);
        {
            const ulonglong2* hp = (const ulonglong2*)&h_buf[rslot][peer_base];
            #pragma unroll
            for (int i = 0; i < 8; ++i) {
                ulonglong2 va = hp[2 * i];
                ulonglong2 vb = hp[2 * i + 1];
                ffma2(acc0, w[32 + 4 * i + 0], va.x);
                ffma2(acc1, w[32 + 4 * i + 1], va.y);
                ffma2(acc2, w[32 + 4 * i + 2], vb.x);
                ffma2(acc3, w[32 + 4 * i + 3], vb.y);
            }
        }
        ull s = fadd2(fadd2(acc0, acc1), fadd2(acc2, acc3));
        float lo = __uint_as_float((uint32_t)s);
        float hi = __uint_as_float((uint32_t)(s >> 32));
        float gate = pre_cur + lo + hi;

        // branch-free activation: sigmoid for i,f,o; tanh for g (= 2*sig(2x)-1)
        float xs = (g == 2) ? two * gate : gate;
        float sv = sigf(xs);
        float a  = (g == 2) ? fmaf(two, sv, -1.0f) : sv;

        // gather gate quad at owner lanes (lane%4==0)
        float af = __shfl_down_sync(0xffffffffu, a, 1);
        float ag = __shfl_down_sync(0xffffffffu, a, 2);
        float ao = __shfl_down_sync(0xffffffffu, a, 3);

        if (owner) {
            c = fmaf(af, c, a * ag);               // a == i for owner lanes
            float h = ao * tanh_fast(c);
            // tx-tracked deliveries: local (own bar_loc) + remote (peer bar_rem)
            st_async_f32(slot ? la1 : la0, h, slot ? lb1c : lb0c);
            st_async_f32(slot ? ra1 : ra0, h, slot ? rb1c : rb0c);
            hs2[(size_t)t * FDIM + m] = h;         // for fc GEMM (fire & forget)
        }
    }

    // Do not exit while peer DSMEM traffic may be in flight
    asm volatile("barrier.cluster.arrive.aligned;" ::: "memory");
    asm volatile("barrier.cluster.wait.aligned;"   ::: "memory");
}

// ---------------------------------------------------------------------------
// launch
// ---------------------------------------------------------------------------
extern "C" void kernel_launch(void* const* d_in, const int* in_sizes, int n_in,
                              void* d_out, int out_size)
{
    (void)in_sizes; (void)n_in; (void)out_size;
    // metadata order: x,h1,c1,h2,c2, Wih1,Whh1,bih1,bhh1, Wih2,Whh2,bih2,bhh2, Wfc,bfc
    const float* x    = (const float*)d_in[0];
    const float* h2   = (const float*)d_in[3];
    const float* c2   = (const float*)d_in[4];
    const float* Wih2 = (const float*)d_in[9];
    const float* Whh2 = (const float*)d_in[10];
    const float* bih2 = (const float*)d_in[11];
    const float* bhh2 = (const float*)d_in[12];
    const float* Wfc  = (const float*)d_in[13];
    const float* bfc  = (const float*)d_in[14];
    float* out = (float*)d_out;

    float* pre2; cudaGetSymbolAddress((void**)&pre2, g_pre2);
    float* hs2;  cudaGetSymbolAddress((void**)&hs2,  g_hs2);

    const int mblocks = (T_STEPS + 63) / 64;   // 782

    // 1) pre2 = x @ Wih2^T + (bih2 + bhh2)   (lstm1 is dead code — skipped)
    gemm_kernel<false, true><<<dim3(HGATE / 64, mblocks), 256>>>(
        x, Wih2, bih2, bhh2, pre2, T_STEPS, HGATE, DIN);

    // 2) sequential LSTM scan over 50000 steps (2-CTA cluster, reg-resident Whh)
    scan_kernel<<<2, 256>>>(pre2, Whh2, h2, c2, hs2);

    // 3) out = sigmoid(hs2 @ Wfc^T + bfc)
    gemm_kernel<true, false><<<dim3(FDIM / 64, mblocks), 256>>>(
        hs2, Wfc, bfc, nullptr, out, T_STEPS, FDIM, FDIM);
}

// round 5
// speedup vs baseline: 1.7126x; 1.0456x over previous
#include <cuda_runtime.h>
#include <cstdint>
#include <cstddef>

// Problem constants
#define T_STEPS 50000
#define DIN     768     // lstm input dim (6*F)
#define HGATE   512     // 4*F gate rows of lstm2
#define FDIM    128     // hidden size of lstm2 / feature dim

// Scratch (device globals; no allocations allowed)
__device__ float g_pre2[(size_t)T_STEPS * HGATE];  // 102.4 MB
__device__ float g_hs2 [(size_t)T_STEPS * FDIM];   //  25.6 MB

typedef unsigned long long ull;

// ---------------------------------------------------------------------------
// helpers
// ---------------------------------------------------------------------------
__device__ __forceinline__ void ffma2(ull& d, ull a, ull b) {
    asm("fma.rn.f32x2 %0, %1, %2, %3;" : "=l"(d) : "l"(a), "l"(b), "l"(d));
}
__device__ __forceinline__ ull fadd2(ull a, ull b) {
    ull d; asm("add.rn.f32x2 %0, %1, %2;" : "=l"(d) : "l"(a), "l"(b)); return d;
}
__device__ __forceinline__ float sigf(float x) {
    return __fdividef(1.0f, 1.0f + __expf(-x));
}
__device__ __forceinline__ float tanh_fast(float x) {
    return fmaf(2.0f, sigf(2.0f * x), -1.0f);
}
__device__ __forceinline__ uint32_t smem_u32(const void* p) {
    uint32_t a;
    asm("{ .reg .u64 t; cvta.to.shared.u64 t, %1; cvt.u32.u64 %0, t; }"
        : "=r"(a) : "l"(p));
    return a;
}
__device__ __forceinline__ uint32_t mapa_u32(uint32_t addr, uint32_t rank) {
    uint32_t r;
    asm("mapa.shared::cluster.u32 %0, %1, %2;" : "=r"(r) : "r"(addr), "r"(rank));
    return r;
}
__device__ __forceinline__ void mbar_expect(uint32_t mbar, uint32_t bytes) {
    asm volatile("mbarrier.arrive.expect_tx.shared.b64 _, [%0], %1;"
                 :: "r"(mbar), "r"(bytes) : "memory");
}
__device__ __forceinline__ void mbar_wait(uint32_t mbar, uint32_t parity) {
    asm volatile(
        "{\n\t.reg .pred P;\n"
        "LW_%=:\n\t"
        "mbarrier.try_wait.parity.shared::cta.b64 P, [%0], %1;\n\t"
        "@P bra LD_%=;\n\t"
        "bra LW_%=;\n"
        "LD_%=:\n\t}"
        :: "r"(mbar), "r"(parity) : "memory");
}
// 256B SMEM->peer-SMEM bulk copy, single tx credit on the peer's mbarrier
__device__ __forceinline__ void bulk_s2s_256(uint32_t dst_cluster, uint32_t src_cta,
                                             uint32_t mbar_cluster) {
    asm volatile(
        "cp.async.bulk.shared::cluster.shared::cta.mbarrier::complete_tx::bytes "
        "[%0], [%1], 256, [%2];"
        :: "r"(dst_cluster), "r"(src_cta), "r"(mbar_cluster) : "memory");
}

// ---------------------------------------------------------------------------
// Generic tiled GEMM: C[M,N] = A[M,K] @ W[N,K]^T + b1[N] (+ b2[N]) (+sigmoid)
// ---------------------------------------------------------------------------
template <bool SIG, bool HASB2>
__global__ __launch_bounds__(256)
void gemm_kernel(const float* __restrict__ A, const float* __restrict__ W,
                 const float* __restrict__ b1, const float* __restrict__ b2,
                 float* __restrict__ C, int M, int N, int K)
{
    __shared__ float As[16][68];
    __shared__ float Bs[16][68];

    const int tid = threadIdx.x;
    const int tx  = tid & 15;
    const int ty  = tid >> 4;
    const int m0  = blockIdx.y * 64;
    const int n0  = blockIdx.x * 64;

    const int lr = tid >> 2;
    const int lk = (tid & 3) * 4;

    const int arow = m0 + lr;
    const int brow = n0 + lr;
    const bool avalid = (arow < M);
    const float* aptr = A + (size_t)arow * K + lk;
    const float* bptr = W + (size_t)brow * K + lk;

    float acc[4][4] = {};

    for (int k0 = 0; k0 < K; k0 += 16) {
        float4 av = avalid ? *(const float4*)(aptr + k0) : make_float4(0.f, 0.f, 0.f, 0.f);
        float4 bv = *(const float4*)(bptr + k0);
        As[lk + 0][lr] = av.x; As[lk + 1][lr] = av.y;
        As[lk + 2][lr] = av.z; As[lk + 3][lr] = av.w;
        Bs[lk + 0][lr] = bv.x; Bs[lk + 1][lr] = bv.y;
        Bs[lk + 2][lr] = bv.z; Bs[lk + 3][lr] = bv.w;
        __syncthreads();
        #pragma unroll
        for (int kk = 0; kk < 16; ++kk) {
            float4 a = *(const float4*)&As[kk][ty * 4];
            float4 b = *(const float4*)&Bs[kk][tx * 4];
            acc[0][0] = fmaf(a.x, b.x, acc[0][0]);
            acc[0][1] = fmaf(a.x, b.y, acc[0][1]);
            acc[0][2] = fmaf(a.x, b.z, acc[0][2]);
            acc[0][3] = fmaf(a.x, b.w, acc[0][3]);
            acc[1][0] = fmaf(a.y, b.x, acc[1][0]);
            acc[1][1] = fmaf(a.y, b.y, acc[1][1]);
            acc[1][2] = fmaf(a.y, b.z, acc[1][2]);
            acc[1][3] = fmaf(a.y, b.w, acc[1][3]);
            acc[2][0] = fmaf(a.z, b.x, acc[2][0]);
            acc[2][1] = fmaf(a.z, b.y, acc[2][1]);
            acc[2][2] = fmaf(a.z, b.z, acc[2][2]);
            acc[2][3] = fmaf(a.z, b.w, acc[2][3]);
            acc[3][0] = fmaf(a.w, b.x, acc[3][0]);
            acc[3][1] = fmaf(a.w, b.y, acc[3][1]);
            acc[3][2] = fmaf(a.w, b.z, acc[3][2]);
            acc[3][3] = fmaf(a.w, b.w, acc[3][3]);
        }
        __syncthreads();
    }

    float bias[4];
    #pragma unroll
    for (int j = 0; j < 4; ++j) {
        int col = n0 + tx * 4 + j;
        bias[j] = b1[col];
        if (HASB2) bias[j] += b2[col];
    }
    #pragma unroll
    for (int i = 0; i < 4; ++i) {
        int row = m0 + ty * 4 + i;
        if (row < M) {
            float4 v;
            v.x = acc[i][0] + bias[0];
            v.y = acc[i][1] + bias[1];
            v.z = acc[i][2] + bias[2];
            v.w = acc[i][3] + bias[3];
            if (SIG) { v.x = sigf(v.x); v.y = sigf(v.y); v.z = sigf(v.z); v.w = sigf(v.w); }
            *(float4*)(C + (size_t)row * N + n0 + tx * 4) = v;
        }
    }
}

// ---------------------------------------------------------------------------
// LSTM2 scan: 2-CTA cluster, lockstep recurrence.
// Per-step messaging reduced to the minimum the HW supports:
//   local  h delivery: STS into h_stage[slot] + the step's single __syncthreads
//   remote h delivery: ONE 256B cp.async.bulk (UBLKCP) -> peer h_peer[slot],
//                      ONE tx credit on the peer's bar[slot]
// (round-3 used 128 st.async messages/step; per-barrier tx accounting
//  serialized them at ~10-15cyc each = the ~1000cyc/step we measured)
//
// Mapping: q = tid>>2 (unit in CTA, 0..63), g = tid&3 (gate i/f/g/o).
// Gate row = g*128 + rank*64 + q; owner lane (g==0) finalizes unit m.
// ---------------------------------------------------------------------------
__global__ void __cluster_dims__(2, 1, 1) __launch_bounds__(256, 1)
scan_kernel(const float* __restrict__ pre2, const float* __restrict__ Whh,
            const float* __restrict__ h0,   const float* __restrict__ c0,
            float* __restrict__ hs2)
{
    __shared__ __align__(32) float h_stage[2][64];   // own CTA's h half
    __shared__ __align__(32) float h_peer [2][64];   // peer CTA's h half (bulk dst)
    __shared__ __align__(8)  unsigned long long bar[2];

    const int tid = threadIdx.x;
    uint32_t rank; asm("mov.u32 %0, %%cluster_ctarank;" : "=r"(rank));
    const uint32_t peer = rank ^ 1u;

    const int q   = tid >> 2;                       // unit within CTA (0..63)
    const int g   = tid & 3;                        // 0:i 1:f 2:g 3:o
    const int row = g * 128 + (int)rank * 64 + q;   // gate row in [0,512)
    const int m   = (int)rank * 64 + q;             // owned hidden unit
    const bool owner = (g == 0);

    const int own_base  = (int)rank * 64;           // h segment owned locally
    const int peer_base = (int)peer * 64;

    // Whh row -> registers: w[0..31] own-half cols, w[32..63] peer-half cols
    ull w[64];
    {
        const ull* wa = (const ull*)(Whh + (size_t)row * FDIM + own_base);
        const ull* wb = (const ull*)(Whh + (size_t)row * FDIM + peer_base);
        #pragma unroll
        for (int i = 0; i < 32; ++i) w[i]      = wa[i];
        #pragma unroll
        for (int i = 0; i < 32; ++i) w[32 + i] = wb[i];
    }

    const uint32_t b0 = smem_u32(&bar[0]);
    const uint32_t b1 = smem_u32(&bar[1]);

    if (tid == 0) {
        asm volatile("mbarrier.init.shared.b64 [%0], %1;" :: "r"(b0), "r"(1) : "memory");
        asm volatile("mbarrier.init.shared.b64 [%0], %1;" :: "r"(b1), "r"(1) : "memory");
    }
    // prestore h0 halves into slot 1 (step 0 reads slot 1)
    if (tid < 64) {
        h_stage[1][tid] = h0[own_base + tid];
        h_peer [1][tid] = h0[peer_base + tid];
    }
    float c = 0.0f;
    if (owner) c = c0[m];

    // tid0 bulk-copy endpoints (both parities)
    uint32_t src0 = 0, src1 = 0, dst0 = 0, dst1 = 0, mb0 = 0, mb1 = 0;
    if (tid == 0) {
        src0 = smem_u32(&h_stage[0][0]);
        src1 = smem_u32(&h_stage[1][0]);
        dst0 = mapa_u32(smem_u32(&h_peer[0][0]), peer);
        dst1 = mapa_u32(smem_u32(&h_peer[1][0]), peer);
        mb0  = mapa_u32(b0, peer);
        mb1  = mapa_u32(b1, peer);
    }

    __syncthreads();
    asm volatile("fence.proxy.async.shared::cta;" ::: "memory");
    // barriers + prestored h visible cluster-wide before any remote traffic
    asm volatile("barrier.cluster.arrive.aligned;" ::: "memory");
    asm volatile("barrier.cluster.wait.aligned;"   ::: "memory");

    // distance-2 prefetch of pre-activations
    const float* prow = pre2 + row;
    float pre_next  = prow[0];
    float pre_next2 = prow[HGATE];
    const float two = 2.0f;

    #pragma unroll 1
    for (int t = 0; t < T_STEPS; ++t) {
        const int slot  = t & 1;        // slot written this step (h[t])
        const int rslot = slot ^ 1;     // slot read this step (h[t-1])

        // Arm this step's incoming-peer barrier (1 credit = one 256B bulk copy).
        if (tid == 0) mbar_expect(slot ? b1 : b0, 256);

        float pre_cur = pre_next;
        pre_next = pre_next2;
        {
            int tn = (t + 2 < T_STEPS) ? (t + 2) : (T_STEPS - 1);
            pre_next2 = __ldg(&prow[(size_t)tn * HGATE]);
        }

        // ---- local half: h_stage[rslot] is ordered by the previous BAR ----
        ull acc0 = 0, acc1 = 0, acc2 = 0, acc3 = 0;
        {
            const ulonglong2* hl = (const ulonglong2*)&h_stage[rslot][0];
            #pragma unroll
            for (int i = 0; i < 8; ++i) {
                ulonglong2 va = hl[2 * i];
                ulonglong2 vb = hl[2 * i + 1];
                ffma2(acc0, w[4 * i + 0], va.x);
                ffma2(acc1, w[4 * i + 1], va.y);
                ffma2(acc2, w[4 * i + 2], vb.x);
                ffma2(acc3, w[4 * i + 3], vb.y);
            }
        }

        // ---- peer half: wait the single bulk-copy credit, then consume ----
        if (t > 0) mbar_wait(rslot ? b1 : b0, (uint32_t)(((t - 1) >> 1) & 1));
        {
            const ulonglong2* hp = (const ulonglong2*)&h_peer[rslot][0];
            #pragma unroll
            for (int i = 0; i < 8; ++i) {
                ulonglong2 va = hp[2 * i];
                ulonglong2 vb = hp[2 * i + 1];
                ffma2(acc0, w[32 + 4 * i + 0], va.x);
                ffma2(acc1, w[32 + 4 * i + 1], va.y);
                ffma2(acc2, w[32 + 4 * i + 2], vb.x);
                ffma2(acc3, w[32 + 4 * i + 3], vb.y);
            }
        }
        ull s = fadd2(fadd2(acc0, acc1), fadd2(acc2, acc3));
        float lo = __uint_as_float((uint32_t)s);
        float hi = __uint_as_float((uint32_t)(s >> 32));
        float gate = pre_cur + lo + hi;

        // branch-free activation: sigmoid for i,f,o; tanh for g (= 2*sig(2x)-1)
        float xs = (g == 2) ? two * gate : gate;
        float sv = sigf(xs);
        float a  = (g == 2) ? fmaf(two, sv, -1.0f) : sv;

        // gather gate quad at owner lanes (lane%4==0)
        float af = __shfl_down_sync(0xffffffffu, a, 1);
        float ag = __shfl_down_sync(0xffffffffu, a, 2);
        float ao = __shfl_down_sync(0xffffffffu, a, 3);

        if (owner) {
            c = fmaf(af, c, a * ag);               // a == i for owner lanes
            float h = ao * tanh_fast(c);
            h_stage[slot][q] = h;                  // local delivery (STS)
            hs2[(size_t)t * FDIM + m] = h;         // for fc GEMM (fire & forget)
        }
        __syncthreads();                           // drains STS; local h[t] visible

        // ---- single 256B bulk copy to peer (one tx credit) ----
        if (tid == 0 && t + 1 < T_STEPS) {
            asm volatile("fence.proxy.async.shared::cta;" ::: "memory");
            bulk_s2s_256(slot ? dst1 : dst0, slot ? src1 : src0, slot ? mb1 : mb0);
        }
    }

    // Do not exit while peer DSMEM traffic may be in flight
    asm volatile("barrier.cluster.arrive.aligned;" ::: "memory");
    asm volatile("barrier.cluster.wait.aligned;"   ::: "memory");
}

// ---------------------------------------------------------------------------
// launch
// ---------------------------------------------------------------------------
extern "C" void kernel_launch(void* const* d_in, const int* in_sizes, int n_in,
                              void* d_out, int out_size)
{
    (void)in_sizes; (void)n_in; (void)out_size;
    // metadata order: x,h1,c1,h2,c2, Wih1,Whh1,bih1,bhh1, Wih2,Whh2,bih2,bhh2, Wfc,bfc
    const float* x    = (const float*)d_in[0];
    const float* h2   = (const float*)d_in[3];
    const float* c2   = (const float*)d_in[4];
    const float* Wih2 = (const float*)d_in[9];
    const float* Whh2 = (const float*)d_in[10];
    const float* bih2 = (const float*)d_in[11];
    const float* bhh2 = (const float*)d_in[12];
    const float* Wfc  = (const float*)d_in[13];
    const float* bfc  = (const float*)d_in[14];
    float* out = (float*)d_out;

    float* pre2; cudaGetSymbolAddress((void**)&pre2, g_pre2);
    float* hs2;  cudaGetSymbolAddress((void**)&hs2,  g_hs2);

    const int mblocks = (T_STEPS + 63) / 64;   // 782

    // 1) pre2 = x @ Wih2^T + (bih2 + bhh2)   (lstm1 is dead code — skipped)
    gemm_kernel<false, true><<<dim3(HGATE / 64, mblocks), 256>>>(
        x, Wih2, bih2, bhh2, pre2, T_STEPS, HGATE, DIN);

    // 2) sequential LSTM scan over 50000 steps (2-CTA cluster, reg-resident Whh)
    scan_kernel<<<2, 256>>>(pre2, Whh2, h2, c2, hs2);

    // 3) out = sigmoid(hs2 @ Wfc^T + bfc)
    gemm_kernel<true, false><<<dim3(FDIM / 64, mblocks), 256>>>(
        hs2, Wfc, bfc, nullptr, out, T_STEPS, FDIM, FDIM);
}

// round 7
// speedup vs baseline: 1.7846x; 1.0420x over previous
#include <cuda_runtime.h>
#include <cstdint>
#include <cstddef>

// Problem constants
#define T_STEPS 50000
#define DIN     768     // lstm input dim (6*F)
#define HGATE   512     // 4*F gate rows of lstm2
#define FDIM    128     // hidden size of lstm2 / feature dim

// Scratch (device globals; no allocations allowed)
__device__ float g_pre2[(size_t)T_STEPS * HGATE];  // 102.4 MB
__device__ float g_hs2 [(size_t)T_STEPS * FDIM];   //  25.6 MB

typedef unsigned long long ull;

// ---------------------------------------------------------------------------
// helpers
// ---------------------------------------------------------------------------
__device__ __forceinline__ void ffma2(ull& d, ull a, ull b) {
    asm("fma.rn.f32x2 %0, %1, %2, %3;" : "=l"(d) : "l"(a), "l"(b), "l"(d));
}
__device__ __forceinline__ ull fadd2(ull a, ull b) {
    ull d; asm("add.rn.f32x2 %0, %1, %2;" : "=l"(d) : "l"(a), "l"(b)); return d;
}
__device__ __forceinline__ float tanh_mufu(float x) {
    float r; asm("tanh.approx.f32 %0, %1;" : "=f"(r) : "f"(x)); return r;
}
__device__ __forceinline__ float sigf(float x) {              // GEMM epilogue only
    return __fdividef(1.0f, 1.0f + __expf(-x));
}
__device__ __forceinline__ uint32_t smem_u32(const void* p) {
    uint32_t a;
    asm("{ .reg .u64 t; cvta.to.shared.u64 t, %1; cvt.u32.u64 %0, t; }"
        : "=r"(a) : "l"(p));
    return a;
}
__device__ __forceinline__ uint32_t mapa_u32(uint32_t addr, uint32_t rank) {
    uint32_t r;
    asm("mapa.shared::cluster.u32 %0, %1, %2;" : "=r"(r) : "r"(addr), "r"(rank));
    return r;
}
__device__ __forceinline__ void mbar_expect(uint32_t mbar, uint32_t bytes) {
    asm volatile("mbarrier.arrive.expect_tx.shared.b64 _, [%0], %1;"
                 :: "r"(mbar), "r"(bytes) : "memory");
}
// plain parity wait — the exact form proven in the round-3/4 passing kernels
__device__ __forceinline__ void mbar_wait(uint32_t mbar, uint32_t parity) {
    asm volatile(
        "{\n\t.reg .pred P;\n"
        "LW_%=:\n\t"
        "mbarrier.try_wait.parity.shared::cta.b64 P, [%0], %1;\n\t"
        "@P bra LD_%=;\n\t"
        "bra LW_%=;\n"
        "LD_%=:\n\t}"
        :: "r"(mbar), "r"(parity) : "memory");
}
// async 4B store to peer SMEM, one 4-byte tx credit on the peer's mbarrier
__device__ __forceinline__ void st_async_f32(uint32_t dst, float v, uint32_t mbar) {
    asm volatile("st.async.shared::cluster.mbarrier::complete_tx::bytes.f32 [%0], %1, [%2];"
                 :: "r"(dst), "f"(v), "r"(mbar) : "memory");
}

// ---------------------------------------------------------------------------
// Generic tiled GEMM: C[M,N] = A[M,K] @ W[N,K]^T + b1[N] (+ b2[N]) (+sigmoid)
// ---------------------------------------------------------------------------
template <bool SIG, bool HASB2>
__global__ __launch_bounds__(256)
void gemm_kernel(const float* __restrict__ A, const float* __restrict__ W,
                 const float* __restrict__ b1, const float* __restrict__ b2,
                 float* __restrict__ C, int M, int N, int K)
{
    __shared__ float As[16][68];
    __shared__ float Bs[16][68];

    const int tid = threadIdx.x;
    const int tx  = tid & 15;
    const int ty  = tid >> 4;
    const int m0  = blockIdx.y * 64;
    const int n0  = blockIdx.x * 64;

    const int lr = tid >> 2;
    const int lk = (tid & 3) * 4;

    const int arow = m0 + lr;
    const int brow = n0 + lr;
    const bool avalid = (arow < M);
    const float* aptr = A + (size_t)arow * K + lk;
    const float* bptr = W + (size_t)brow * K + lk;

    float acc[4][4] = {};

    for (int k0 = 0; k0 < K; k0 += 16) {
        float4 av = avalid ? *(const float4*)(aptr + k0) : make_float4(0.f, 0.f, 0.f, 0.f);
        float4 bv = *(const float4*)(bptr + k0);
        As[lk + 0][lr] = av.x; As[lk + 1][lr] = av.y;
        As[lk + 2][lr] = av.z; As[lk + 3][lr] = av.w;
        Bs[lk + 0][lr] = bv.x; Bs[lk + 1][lr] = bv.y;
        Bs[lk + 2][lr] = bv.z; Bs[lk + 3][lr] = bv.w;
        __syncthreads();
        #pragma unroll
        for (int kk = 0; kk < 16; ++kk) {
            float4 a = *(const float4*)&As[kk][ty * 4];
            float4 b = *(const float4*)&Bs[kk][tx * 4];
            acc[0][0] = fmaf(a.x, b.x, acc[0][0]);
            acc[0][1] = fmaf(a.x, b.y, acc[0][1]);
            acc[0][2] = fmaf(a.x, b.z, acc[0][2]);
            acc[0][3] = fmaf(a.x, b.w, acc[0][3]);
            acc[1][0] = fmaf(a.y, b.x, acc[1][0]);
            acc[1][1] = fmaf(a.y, b.y, acc[1][1]);
            acc[1][2] = fmaf(a.y, b.z, acc[1][2]);
            acc[1][3] = fmaf(a.y, b.w, acc[1][3]);
            acc[2][0] = fmaf(a.z, b.x, acc[2][0]);
            acc[2][1] = fmaf(a.z, b.y, acc[2][1]);
            acc[2][2] = fmaf(a.z, b.z, acc[2][2]);
            acc[2][3] = fmaf(a.z, b.w, acc[2][3]);
            acc[3][0] = fmaf(a.w, b.x, acc[3][0]);
            acc[3][1] = fmaf(a.w, b.y, acc[3][1]);
            acc[3][2] = fmaf(a.w, b.z, acc[3][2]);
            acc[3][3] = fmaf(a.w, b.w, acc[3][3]);
        }
        __syncthreads();
    }

    float bias[4];
    #pragma unroll
    for (int j = 0; j < 4; ++j) {
        int col = n0 + tx * 4 + j;
        bias[j] = b1[col];
        if (HASB2) bias[j] += b2[col];
    }
    #pragma unroll
    for (int i = 0; i < 4; ++i) {
        int row = m0 + ty * 4 + i;
        if (row < M) {
            float4 v;
            v.x = acc[i][0] + bias[0];
            v.y = acc[i][1] + bias[1];
            v.z = acc[i][2] + bias[2];
            v.w = acc[i][3] + bias[3];
            if (SIG) { v.x = sigf(v.x); v.y = sigf(v.y); v.z = sigf(v.z); v.w = sigf(v.w); }
            *(float4*)(C + (size_t)row * N + n0 + tx * 4) = v;
        }
    }
}

// ---------------------------------------------------------------------------
// LSTM2 scan: 2-CTA cluster, lockstep recurrence.
//   local  h delivery: STS into h_stage[slot] + one __syncthreads
//   remote h delivery: 64 owner-issued st.async f32 at h-compute time
//   activations: MUFU.TANH (single-MUFU sigmoid/tanh) at both serial sites
// Mapping: q = tid>>2 (unit in CTA, 0..63), g = tid&3 (gate i/f/g/o).
// ---------------------------------------------------------------------------
__global__ void __cluster_dims__(2, 1, 1) __launch_bounds__(256, 1)
scan_kernel(const float* __restrict__ pre2, const float* __restrict__ Whh,
            const float* __restrict__ h0,   const float* __restrict__ c0,
            float* __restrict__ hs2)
{
    __shared__ __align__(32) float h_stage[2][64];   // own CTA's h half
    __shared__ __align__(32) float h_peer [2][64];   // peer CTA's h half (st.async dst)
    __shared__ __align__(8)  unsigned long long bar[2];

    const int tid = threadIdx.x;
    uint32_t rank; asm("mov.u32 %0, %%cluster_ctarank;" : "=r"(rank));
    const uint32_t peer = rank ^ 1u;

    const int q   = tid >> 2;                       // unit within CTA (0..63)
    const int g   = tid & 3;                        // 0:i 1:f 2:g 3:o
    const int row = g * 128 + (int)rank * 64 + q;   // gate row in [0,512)
    const int m   = (int)rank * 64 + q;             // owned hidden unit
    const bool owner = (g == 0);

    const int own_base  = (int)rank * 64;
    const int peer_base = (int)peer * 64;

    // Whh row -> registers: w[0..31] own-half cols, w[32..63] peer-half cols
    ull w[64];
    {
        const ull* wa = (const ull*)(Whh + (size_t)row * FDIM + own_base);
        const ull* wb = (const ull*)(Whh + (size_t)row * FDIM + peer_base);
        #pragma unroll
        for (int i = 0; i < 32; ++i) w[i]      = wa[i];
        #pragma unroll
        for (int i = 0; i < 32; ++i) w[32 + i] = wb[i];
    }

    const uint32_t b0 = smem_u32(&bar[0]);
    const uint32_t b1 = smem_u32(&bar[1]);

    if (tid == 0) {
        asm volatile("mbarrier.init.shared.b64 [%0], %1;" :: "r"(b0), "r"(1) : "memory");
        asm volatile("mbarrier.init.shared.b64 [%0], %1;" :: "r"(b1), "r"(1) : "memory");
    }
    // prestore h0 halves into slot 1 (step 0 reads slot 1)
    if (tid < 64) {
        h_stage[1][tid] = h0[own_base + tid];
        h_peer [1][tid] = h0[peer_base + tid];
    }
    float c = 0.0f;
    if (owner) c = c0[m];

    // Owner remote destinations: peer's h_peer[slot][q] + peer's bar[slot]
    uint32_t rdst0 = 0, rdst1 = 0, rmb0 = 0, rmb1 = 0;
    if (owner) {
        rdst0 = mapa_u32(smem_u32(&h_peer[0][q]), peer);
        rdst1 = mapa_u32(smem_u32(&h_peer[1][q]), peer);
        rmb0  = mapa_u32(b0, peer);
        rmb1  = mapa_u32(b1, peer);
    }

    // per-thread activation constants (gate g uses tanh, others sigmoid)
    const float k_in  = (g == 2) ? 1.0f : 0.5f;
    const float k_out = (g == 2) ? 1.0f : 0.5f;
    const float k_add = (g == 2) ? 0.0f : 0.5f;

    __syncthreads();
    asm volatile("fence.proxy.async.shared::cta;" ::: "memory");
    asm volatile("barrier.cluster.arrive.aligned;" ::: "memory");
    asm volatile("barrier.cluster.wait.aligned;"   ::: "memory");

    // distance-2 prefetch of pre-activations
    const float* prow = pre2 + row;
    float pre_next  = prow[0];
    float pre_next2 = prow[HGATE];

    #pragma unroll 1
    for (int t = 0; t < T_STEPS; ++t) {
        const int slot  = t & 1;        // slot written this step (h[t])
        const int rslot = slot ^ 1;     // slot read this step (h[t-1])

        // Arm barrier for THIS step's incoming peer h (credits landing before
        // arming are safe: tx-count underflow is legal per PTX).
        if (tid == 0) mbar_expect(slot ? b1 : b0, 256);

        float pre_cur = pre_next;
        pre_next = pre_next2;
        {
            int tn = (t + 2 < T_STEPS) ? (t + 2) : (T_STEPS - 1);
            pre_next2 = __ldg(&prow[(size_t)tn * HGATE]);
        }

        // ---- local half (ordered by previous BAR); acc0 seeded with pre ----
        ull acc0 = (ull)(uint32_t)__float_as_uint(pre_cur);
        ull acc1 = 0, acc2 = 0, acc3 = 0;
        {
            const ulonglong2* hl = (const ulonglong2*)&h_stage[rslot][0];
            #pragma unroll
            for (int i = 0; i < 8; ++i) {
                ulonglong2 va = hl[2 * i];
                ulonglong2 vb = hl[2 * i + 1];
                ffma2(acc0, w[4 * i + 0], va.x);
                ffma2(acc1, w[4 * i + 1], va.y);
                ffma2(acc2, w[4 * i + 2], vb.x);
                ffma2(acc3, w[4 * i + 3], vb.y);
            }
        }

        // ---- peer half: wait 256B of owner st.async credits ----
        if (t > 0) mbar_wait(rslot ? b1 : b0, (uint32_t)(((t - 1) >> 1) & 1));
        {
            const ulonglong2* hp = (const ulonglong2*)&h_peer[rslot][0];
            #pragma unroll
            for (int i = 0; i < 8; ++i) {
                ulonglong2 va = hp[2 * i];
                ulonglong2 vb = hp[2 * i + 1];
                ffma2(acc0, w[32 + 4 * i + 0], va.x);
                ffma2(acc1, w[32 + 4 * i + 1], va.y);
                ffma2(acc2, w[32 + 4 * i + 2], vb.x);
                ffma2(acc3, w[32 + 4 * i + 3], vb.y);
            }
        }
        ull s = fadd2(fadd2(acc0, acc1), fadd2(acc2, acc3));
        float lo = __uint_as_float((uint32_t)s);
        float hi = __uint_as_float((uint32_t)(s >> 32));
        float gate = lo + hi;

        // single-MUFU activation (tanh for g, sigmoid-via-tanh for i/f/o)
        float a = fmaf(k_out, tanh_mufu(k_in * gate), k_add);

        // gather gate quad at owner lanes (lane%4==0)
        float af = __shfl_down_sync(0xffffffffu, a, 1);
        float ag = __shfl_down_sync(0xffffffffu, a, 2);
        float ao = __shfl_down_sync(0xffffffffu, a, 3);

        if (owner) {
            c = fmaf(af, c, a * ag);               // a == i for owner lanes
            float h = ao * tanh_mufu(c);
            // remote delivery starts NOW (flight overlaps activation/BAR below)
            st_async_f32(slot ? rdst1 : rdst0, h, slot ? rmb1 : rmb0);
            h_stage[slot][q] = h;                  // local delivery (STS)
            hs2[(size_t)t * FDIM + m] = h;         // for fc GEMM (fire & forget)
        }
        __syncthreads();                           // drains STS; local h[t] visible
    }

    // Do not exit while peer DSMEM traffic may be in flight
    asm volatile("barrier.cluster.arrive.aligned;" ::: "memory");
    asm volatile("barrier.cluster.wait.aligned;"   ::: "memory");
}

// ---------------------------------------------------------------------------
// launch
// ---------------------------------------------------------------------------
extern "C" void kernel_launch(void* const* d_in, const int* in_sizes, int n_in,
                              void* d_out, int out_size)
{
    (void)in_sizes; (void)n_in; (void)out_size;
    // metadata order: x,h1,c1,h2,c2, Wih1,Whh1,bih1,bhh1, Wih2,Whh2,bih2,bhh2, Wfc,bfc
    const float* x    = (const float*)d_in[0];
    const float* h2   = (const float*)d_in[3];
    const float* c2   = (const float*)d_in[4];
    const float* Wih2 = (const float*)d_in[9];
    const float* Whh2 = (const float*)d_in[10];
    const float* bih2 = (const float*)d_in[11];
    const float* bhh2 = (const float*)d_in[12];
    const float* Wfc  = (const float*)d_in[13];
    const float* bfc  = (const float*)d_in[14];
    float* out = (float*)d_out;

    float* pre2; cudaGetSymbolAddress((void**)&pre2, g_pre2);
    float* hs2;  cudaGetSymbolAddress((void**)&hs2,  g_hs2);

    const int mblocks = (T_STEPS + 63) / 64;   // 782

    // 1) pre2 = x @ Wih2^T + (bih2 + bhh2)   (lstm1 is dead code — skipped)
    gemm_kernel<false, true><<<dim3(HGATE / 64, mblocks), 256>>>(
        x, Wih2, bih2, bhh2, pre2, T_STEPS, HGATE, DIN);

    // 2) sequential LSTM scan over 50000 steps (2-CTA cluster, reg-resident Whh)
    scan_kernel<<<2, 256>>>(pre2, Whh2, h2, c2, hs2);

    // 3) out = sigmoid(hs2 @ Wfc^T + bfc)
    gemm_kernel<true, false><<<dim3(FDIM / 64, mblocks), 256>>>(
        hs2, Wfc, bfc, nullptr, out, T_STEPS, FDIM, FDIM);
}

// round 9
// speedup vs baseline: 1.9866x; 1.1132x over previous
#include <cuda_runtime.h>
#include <cstdint>
#include <cstddef>

// Problem constants
#define T_STEPS 50000
#define DIN     768     // lstm input dim (6*F)
#define HGATE   512     // 4*F gate rows of lstm2
#define FDIM    128     // hidden size of lstm2 / feature dim
#define CLUST   4       // scan cluster size
#define UPC     32      // hidden units per CTA (FDIM / CLUST)

// Scratch (device globals; no allocations allowed)
__device__ float g_pre2[(size_t)T_STEPS * HGATE];  // 102.4 MB
__device__ float g_hs2 [(size_t)T_STEPS * FDIM];   //  25.6 MB

typedef unsigned long long ull;

// ---------------------------------------------------------------------------
// helpers (only asm forms proven in previously PASSING kernels)
// ---------------------------------------------------------------------------
__device__ __forceinline__ void ffma2(ull& d, ull a, ull b) {
    asm("fma.rn.f32x2 %0, %1, %2, %3;" : "=l"(d) : "l"(a), "l"(b), "l"(d));
}
__device__ __forceinline__ ull fadd2(ull a, ull b) {
    ull d; asm("add.rn.f32x2 %0, %1, %2;" : "=l"(d) : "l"(a), "l"(b)); return d;
}
__device__ __forceinline__ float tanh_mufu(float x) {
    float r; asm("tanh.approx.f32 %0, %1;" : "=f"(r) : "f"(x)); return r;
}
__device__ __forceinline__ float sigf(float x) {              // GEMM epilogue only
    return __fdividef(1.0f, 1.0f + __expf(-x));
}
__device__ __forceinline__ uint32_t smem_u32(const void* p) {
    uint32_t a;
    asm("{ .reg .u64 t; cvta.to.shared.u64 t, %1; cvt.u32.u64 %0, t; }"
        : "=r"(a) : "l"(p));
    return a;
}
__device__ __forceinline__ uint32_t mapa_u32(uint32_t addr, uint32_t rank) {
    uint32_t r;
    asm("mapa.shared::cluster.u32 %0, %1, %2;" : "=r"(r) : "r"(addr), "r"(rank));
    return r;
}
__device__ __forceinline__ void mbar_expect(uint32_t mbar, uint32_t bytes) {
    asm volatile("mbarrier.arrive.expect_tx.shared.b64 _, [%0], %1;"
                 :: "r"(mbar), "r"(bytes) : "memory");
}
// plain parity wait — exact form proven in rounds 3/4/5/7
__device__ __forceinline__ void mbar_wait(uint32_t mbar, uint32_t parity) {
    asm volatile(
        "{\n\t.reg .pred P;\n"
        "LW_%=:\n\t"
        "mbarrier.try_wait.parity.shared::cta.b64 P, [%0], %1;\n\t"
        "@P bra LD_%=;\n\t"
        "bra LW_%=;\n"
        "LD_%=:\n\t}"
        :: "r"(mbar), "r"(parity) : "memory");
}
// async 4B store to peer SMEM, 4-byte tx credit on the peer's mbarrier
__device__ __forceinline__ void st_async_f32(uint32_t dst, float v, uint32_t mbar) {
    asm volatile("st.async.shared::cluster.mbarrier::complete_tx::bytes.f32 [%0], %1, [%2];"
                 :: "r"(dst), "f"(v), "r"(mbar) : "memory");
}
// pure-C++ packed pair (no new asm): lo -> bits[0:32), hi -> bits[32:64)
__device__ __forceinline__ ull pack_f2(float lo, float hi) {
    return ((ull)__float_as_uint(hi) << 32) | (ull)__float_as_uint(lo);
}

// ---------------------------------------------------------------------------
// Generic tiled GEMM: C[M,N] = A[M,K] @ W[N,K]^T + b1[N] (+ b2[N]) (+sigmoid)
// ---------------------------------------------------------------------------
template <bool SIG, bool HASB2>
__global__ __launch_bounds__(256)
void gemm_kernel(const float* __restrict__ A, const float* __restrict__ W,
                 const float* __restrict__ b1, const float* __restrict__ b2,
                 float* __restrict__ C, int M, int N, int K)
{
    __shared__ float As[16][68];
    __shared__ float Bs[16][68];

    const int tid = threadIdx.x;
    const int tx  = tid & 15;
    const int ty  = tid >> 4;
    const int m0  = blockIdx.y * 64;
    const int n0  = blockIdx.x * 64;

    const int lr = tid >> 2;
    const int lk = (tid & 3) * 4;

    const int arow = m0 + lr;
    const int brow = n0 + lr;
    const bool avalid = (arow < M);
    const float* aptr = A + (size_t)arow * K + lk;
    const float* bptr = W + (size_t)brow * K + lk;

    float acc[4][4] = {};

    for (int k0 = 0; k0 < K; k0 += 16) {
        float4 av = avalid ? *(const float4*)(aptr + k0) : make_float4(0.f, 0.f, 0.f, 0.f);
        float4 bv = *(const float4*)(bptr + k0);
        As[lk + 0][lr] = av.x; As[lk + 1][lr] = av.y;
        As[lk + 2][lr] = av.z; As[lk + 3][lr] = av.w;
        Bs[lk + 0][lr] = bv.x; Bs[lk + 1][lr] = bv.y;
        Bs[lk + 2][lr] = bv.z; Bs[lk + 3][lr] = bv.w;
        __syncthreads();
        #pragma unroll
        for (int kk = 0; kk < 16; ++kk) {
            float4 a = *(const float4*)&As[kk][ty * 4];
            float4 b = *(const float4*)&Bs[kk][tx * 4];
            acc[0][0] = fmaf(a.x, b.x, acc[0][0]);
            acc[0][1] = fmaf(a.x, b.y, acc[0][1]);
            acc[0][2] = fmaf(a.x, b.z, acc[0][2]);
            acc[0][3] = fmaf(a.x, b.w, acc[0][3]);
            acc[1][0] = fmaf(a.y, b.x, acc[1][0]);
            acc[1][1] = fmaf(a.y, b.y, acc[1][1]);
            acc[1][2] = fmaf(a.y, b.z, acc[1][2]);
            acc[1][3] = fmaf(a.y, b.w, acc[1][3]);
            acc[2][0] = fmaf(a.z, b.x, acc[2][0]);
            acc[2][1] = fmaf(a.z, b.y, acc[2][1]);
            acc[2][2] = fmaf(a.z, b.z, acc[2][2]);
            acc[2][3] = fmaf(a.z, b.w, acc[2][3]);
            acc[3][0] = fmaf(a.w, b.x, acc[3][0]);
            acc[3][1] = fmaf(a.w, b.y, acc[3][1]);
            acc[3][2] = fmaf(a.w, b.z, acc[3][2]);
            acc[3][3] = fmaf(a.w, b.w, acc[3][3]);
        }
        __syncthreads();
    }

    float bias[4];
    #pragma unroll
    for (int j = 0; j < 4; ++j) {
        int col = n0 + tx * 4 + j;
        bias[j] = b1[col];
        if (HASB2) bias[j] += b2[col];
    }
    #pragma unroll
    for (int i = 0; i < 4; ++i) {
        int row = m0 + ty * 4 + i;
        if (row < M) {
            float4 v;
            v.x = acc[i][0] + bias[0];
            v.y = acc[i][1] + bias[1];
            v.z = acc[i][2] + bias[2];
            v.w = acc[i][3] + bias[3];
            if (SIG) { v.x = sigf(v.x); v.y = sigf(v.y); v.z = sigf(v.z); v.w = sigf(v.w); }
            *(float4*)(C + (size_t)row * N + n0 + tx * 4) = v;
        }
    }
}

// ---------------------------------------------------------------------------
// LSTM2 scan: 4-CTA cluster. Each CTA owns 32 hidden units = 128 gate rows;
// 128 threads, one full 128-wide Whh row per thread in registers.
// Per-SMSP FFMA issue floor halved vs the 2-CTA version (1 warp/SMSP).
//   local  h delivery: STS + one __syncthreads
//   remote h delivery: owners st.async to 3 peers; ONE barrier, 384B credits
//   own-segment FFMAs run before the wait to hide the DSMEM flight
// Index spaces: ull index u in [0,64) over h (2 floats each). Own segment is
// ull [BASE_U, BASE_U+16). Peer weights/values walk the circular order
// (BASE_U+16+k)&63, k=0..47 — weights and h reads use the SAME formula.
// ---------------------------------------------------------------------------
template <int RANK>
__device__ __forceinline__ void scan_impl(
    const float* __restrict__ pre2, const float* __restrict__ Whh,
    const float* __restrict__ h0,   const float* __restrict__ c0,
    float* __restrict__ hs2,
    float (*h_buf)[FDIM], unsigned long long* bar_rem)
{
    const int tid = threadIdx.x;
    const int q   = tid >> 2;                  // unit within CTA (0..31)
    const int g   = tid & 3;                   // 0:i 1:f 2:g 3:o
    const int row = g * FDIM + RANK * UPC + q; // gate row in [0,512)
    const int m   = RANK * UPC + q;            // owned hidden unit
    const bool owner = (g == 0);

    constexpr int BASE_F = RANK * UPC;         // own float base (mult of 32)
    constexpr int BASE_U = RANK * (UPC / 2);   // own ull base   (mult of 16)

    // fold the sigmoid 0.5 input scale into weights & pre at init
    const float k_in  = (g == 2) ? 1.0f : 0.5f;
    const float k_out = (g == 2) ? 1.0f : 0.5f;
    const float k_add = (g == 2) ? 0.0f : 0.5f;

    // Whh row -> registers: w[0..15] = own ulls, w[16..63] = circular rest
    ull w[64];
    {
        const float2* wr = (const float2*)(Whh + (size_t)row * FDIM);
        #pragma unroll
        for (int i = 0; i < 16; ++i) {
            float2 v = wr[BASE_U + i];
            w[i] = pack_f2(v.x * k_in, v.y * k_in);
        }
        #pragma unroll
        for (int k = 0; k < 48; ++k) {
            float2 v = wr[(BASE_U + 16 + k) & 63];
            w[16 + k] = pack_f2(v.x * k_in, v.y * k_in);
        }
    }

    const uint32_t b0 = smem_u32(&bar_rem[0]);
    const uint32_t b1 = smem_u32(&bar_rem[1]);

    if (tid == 0) {
        asm volatile("mbarrier.init.shared.b64 [%0], %1;" :: "r"(b0), "r"(1) : "memory");
        asm volatile("mbarrier.init.shared.b64 [%0], %1;" :: "r"(b1), "r"(1) : "memory");
    }
    // prestore full h0 into slot 1 (step 0 reads slot 1)
    h_buf[1][tid] = h0[tid];
    float c = 0.0f;
    if (owner) c = c0[m];

    // Owner remote destinations: 3 peers x 2 slots (h slot addr + peer bar)
    uint32_t rdst[3][2], rmb[3][2];
    if (owner) {
        uint32_t a0 = smem_u32(&h_buf[0][m]);
        uint32_t a1 = smem_u32(&h_buf[1][m]);
        #pragma unroll
        for (int p = 0; p < 3; ++p) {
            uint32_t pr = ((uint32_t)RANK + 1u + p) & 3u;
            rdst[p][0] = mapa_u32(a0, pr);
            rdst[p][1] = mapa_u32(a1, pr);
            rmb [p][0] = mapa_u32(b0, pr);
            rmb [p][1] = mapa_u32(b1, pr);
        }
    }

    __syncthreads();
    asm volatile("fence.proxy.async.shared::cta;" ::: "memory");
    asm volatile("barrier.cluster.arrive.aligned;" ::: "memory");
    asm volatile("barrier.cluster.wait.aligned;"   ::: "memory");

    // distance-2 prefetch of pre-activations (pre-scaled by k_in)
    const float* prow = pre2 + row;
    float pre_next  = prow[0] * k_in;
    float pre_next2 = prow[HGATE] * k_in;

    #pragma unroll 1
    for (int t = 0; t < T_STEPS; ++t) {
        const int slot  = t & 1;        // slot written this step (h[t])
        const int rslot = slot ^ 1;     // slot read this step (h[t-1])

        // Arm this step's incoming-peer barrier: 3 peers x 32 owners x 4B.
        // (credits landing before arming are safe: tx underflow is legal)
        if (tid == 0) mbar_expect(slot ? b1 : b0, 3 * UPC * 4);

        float pre_cur = pre_next;
        pre_next = pre_next2;
        {
            int tn = (t + 2 < T_STEPS) ? (t + 2) : (T_STEPS - 1);
            pre_next2 = __ldg(&prow[(size_t)tn * HGATE]) * k_in;
        }

        // ---- own segment (32 h values, ordered by previous BAR) ----
        ull acc0 = (ull)(uint32_t)__float_as_uint(pre_cur);
        ull acc1 = 0, acc2 = 0, acc3 = 0;
        {
            const ulonglong2* hl = (const ulonglong2*)&h_buf[rslot][BASE_F];
            #pragma unroll
            for (int i = 0; i < 4; ++i) {
                ulonglong2 va = hl[2 * i];
                ulonglong2 vb = hl[2 * i + 1];
                ffma2(acc0, w[4 * i + 0], va.x);
                ffma2(acc1, w[4 * i + 1], va.y);
                ffma2(acc2, w[4 * i + 2], vb.x);
                ffma2(acc3, w[4 * i + 3], vb.y);
            }
        }

        // ---- peer segments: wait 384B of st.async credits, then 96 values.
        //      h ull-index formula matches the w[16+k] load formula exactly:
        //      uidx = (BASE_U+16+2j)&63 is even => 16B-aligned, no pair wrap.
        if (t > 0) mbar_wait(rslot ? b1 : b0, (uint32_t)(((t - 1) >> 1) & 1));
        {
            const ull* hu = (const ull*)&h_buf[rslot][0];
            #pragma unroll
            for (int j = 0; j < 24; ++j) {
                const int uidx = (BASE_U + 16 + 2 * j) & 63;   // constant-folded
                ulonglong2 v = *(const ulonglong2*)&hu[uidx];
                ffma2(((j & 1) ? acc1 : acc0), w[16 + 2 * j + 0], v.x);
                ffma2(((j & 1) ? acc3 : acc2), w[16 + 2 * j + 1], v.y);
            }
        }
        ull s = fadd2(fadd2(acc0, acc1), fadd2(acc2, acc3));
        float lo = __uint_as_float((uint32_t)s);
        float hi = __uint_as_float((uint32_t)(s >> 32));
        float gate = lo + hi;   // already scaled by k_in

        // single-MUFU activation (tanh for g, sigmoid-via-tanh for i/f/o)
        float a = fmaf(k_out, tanh_mufu(gate), k_add);

        // gather gate quad at owner lanes (lane%4==0)
        float af = __shfl_down_sync(0xffffffffu, a, 1);
        float ag = __shfl_down_sync(0xffffffffu, a, 2);
        float ao = __shfl_down_sync(0xffffffffu, a, 3);

        if (owner) {
            c = fmaf(af, c, a * ag);               // a == i for owner lanes
            float h = ao * tanh_mufu(c);
            // remote deliveries to 3 peers (flight overlaps BAR + next local)
            st_async_f32(rdst[0][slot], h, rmb[0][slot]);
            st_async_f32(rdst[1][slot], h, rmb[1][slot]);
            st_async_f32(rdst[2][slot], h, rmb[2][slot]);
            h_buf[slot][m] = h;                    // local delivery (STS)
            hs2[(size_t)t * FDIM + m] = h;         // for fc GEMM (fire & forget)
        }
        __syncthreads();                           // drains STS; local h[t] visible
    }

    asm volatile("barrier.cluster.arrive.aligned;" ::: "memory");
    asm volatile("barrier.cluster.wait.aligned;"   ::: "memory");
}

__global__ void __cluster_dims__(CLUST, 1, 1) __launch_bounds__(128, 1)
scan_kernel(const float* __restrict__ pre2, const float* __restrict__ Whh,
            const float* __restrict__ h0,   const float* __restrict__ c0,
            float* __restrict__ hs2)
{
    __shared__ __align__(16) float h_buf[2][FDIM];
    __shared__ __align__(8)  unsigned long long bar_rem[2];

    uint32_t rank; asm("mov.u32 %0, %%cluster_ctarank;" : "=r"(rank));
    switch (rank) {
        case 0: scan_impl<0>(pre2, Whh, h0, c0, hs2, h_buf, bar_rem); break;
        case 1: scan_impl<1>(pre2, Whh, h0, c0, hs2, h_buf, bar_rem); break;
        case 2: scan_impl<2>(pre2, Whh, h0, c0, hs2, h_buf, bar_rem); break;
        default: scan_impl<3>(pre2, Whh, h0, c0, hs2, h_buf, bar_rem); break;
    }
}

// ---------------------------------------------------------------------------
// launch
// ---------------------------------------------------------------------------
extern "C" void kernel_launch(void* const* d_in, const int* in_sizes, int n_in,
                              void* d_out, int out_size)
{
    (void)in_sizes; (void)n_in; (void)out_size;
    // metadata order: x,h1,c1,h2,c2, Wih1,Whh1,bih1,bhh1, Wih2,Whh2,bih2,bhh2, Wfc,bfc
    const float* x    = (const float*)d_in[0];
    const float* h2   = (const float*)d_in[3];
    const float* c2   = (const float*)d_in[4];
    const float* Wih2 = (const float*)d_in[9];
    const float* Whh2 = (const float*)d_in[10];
    const float* bih2 = (const float*)d_in[11];
    const float* bhh2 = (const float*)d_in[12];
    const float* Wfc  = (const float*)d_in[13];
    const float* bfc  = (const float*)d_in[14];
    float* out = (float*)d_out;

    float* pre2; cudaGetSymbolAddress((void**)&pre2, g_pre2);
    float* hs2;  cudaGetSymbolAddress((void**)&hs2,  g_hs2);

    const int mblocks = (T_STEPS + 63) / 64;   // 782

    // 1) pre2 = x @ Wih2^T + (bih2 + bhh2)   (lstm1 is dead code — skipped)
    gemm_kernel<false, true><<<dim3(HGATE / 64, mblocks), 256>>>(
        x, Wih2, bih2, bhh2, pre2, T_STEPS, HGATE, DIN);

    // 2) sequential LSTM scan over 50000 steps (4-CTA cluster, reg-resident Whh)
    scan_kernel<<<CLUST, 128>>>(pre2, Whh2, h2, c2, hs2);

    // 3) out = sigmoid(hs2 @ Wfc^T + bfc)
    gemm_kernel<true, false><<<dim3(FDIM / 64, mblocks), 256>>>(
        hs2, Wfc, bfc, nullptr, out, T_STEPS, FDIM, FDIM);
}